// round 1
// baseline (speedup 1.0000x reference)
#include <cuda_runtime.h>
#include <math.h>

#define D   1024
#define T1  8192
#define T2  4096
#define TT  12288

// -------- scratch (device globals; no allocation anywhere) --------
__device__ float g_xcat[TT * D];          // concatenated input tokens
__device__ float g_h[TT * D];             // LN output (reused for LN1 and LN2)
__device__ float g_qkv[TT * 3 * D];       // qkv projections
__device__ float g_o[TT * D];             // attention output
__device__ float g_xa[TT * D];            // x after attention residual
__device__ float g_u[TT * 4 * D];         // MLP hidden

// ---------------- LayerNorm ----------------
__global__ __launch_bounds__(256) void ln_kernel(
    const float* __restrict__ x, const float* __restrict__ g,
    const float* __restrict__ b, float* __restrict__ out)
{
    int t = blockIdx.x;
    const float4* xr = (const float4*)(x + (size_t)t * D);
    float4 v = xr[threadIdx.x];
    float s  = v.x + v.y + v.z + v.w;
    float s2 = v.x*v.x + v.y*v.y + v.z*v.z + v.w*v.w;
    #pragma unroll
    for (int o = 16; o > 0; o >>= 1) {
        s  += __shfl_xor_sync(0xffffffffu, s,  o);
        s2 += __shfl_xor_sync(0xffffffffu, s2, o);
    }
    __shared__ float2 wr[8];
    __shared__ float2 stat;
    int warp = threadIdx.x >> 5, lane = threadIdx.x & 31;
    if (lane == 0) wr[warp] = make_float2(s, s2);
    __syncthreads();
    if (threadIdx.x == 0) {
        float ts = 0.f, ts2 = 0.f;
        #pragma unroll
        for (int i = 0; i < 8; i++) { ts += wr[i].x; ts2 += wr[i].y; }
        float mu  = ts * (1.0f / D);
        float var = ts2 * (1.0f / D) - mu * mu;
        stat = make_float2(mu, rsqrtf(var + 1e-5f));
    }
    __syncthreads();
    float mu = stat.x, rstd = stat.y;
    float4 gv = ((const float4*)g)[threadIdx.x];
    float4 bv = ((const float4*)b)[threadIdx.x];
    float4 o4;
    o4.x = (v.x - mu) * rstd * gv.x + bv.x;
    o4.y = (v.y - mu) * rstd * gv.y + bv.y;
    o4.z = (v.z - mu) * rstd * gv.z + bv.z;
    o4.w = (v.w - mu) * rstd * gv.w + bv.w;
    ((float4*)(out + (size_t)t * D))[threadIdx.x] = o4;
}

// ---------------- SGEMM: C = A[MxK] @ B[KxN] + bias (+epilogue) ----------------
// EPI: 0 = bias only, 1 = bias + QuickGELU, 2 = bias + residual add
template<int EPI>
__global__ __launch_bounds__(256) void sgemm_kernel(
    const float* __restrict__ A, const float* __restrict__ B,
    const float* __restrict__ bias, const float* __restrict__ res,
    float* __restrict__ C, int M, int N, int K)
{
    __shared__ float As[8][128];   // [k][row]
    __shared__ float Bs[8][128];   // [k][col]
    int tid  = threadIdx.x;
    int row0 = blockIdx.y * 128, col0 = blockIdx.x * 128;
    int tx = tid & 15, ty = tid >> 4;

    float acc[8][8];
    #pragma unroll
    for (int i = 0; i < 8; i++)
        #pragma unroll
        for (int j = 0; j < 8; j++) acc[i][j] = 0.f;

    int arow = tid >> 1,  ak   = (tid & 1) * 4;
    int bk   = tid >> 5,  bcol = (tid & 31) * 4;
    const float* Ap = A + (size_t)(row0 + arow) * K + ak;
    const float* Bp = B + (size_t)bk * N + col0 + bcol;

    for (int k0 = 0; k0 < K; k0 += 8) {
        float4 av = *(const float4*)(Ap + k0);
        float4 bv = *(const float4*)(Bp + (size_t)k0 * N);
        As[ak + 0][arow] = av.x; As[ak + 1][arow] = av.y;
        As[ak + 2][arow] = av.z; As[ak + 3][arow] = av.w;
        *(float4*)&Bs[bk][bcol] = bv;
        __syncthreads();
        #pragma unroll
        for (int k = 0; k < 8; k++) {
            float4 a0 = *(const float4*)&As[k][ty * 8];
            float4 a1 = *(const float4*)&As[k][ty * 8 + 4];
            float4 b0 = *(const float4*)&Bs[k][tx * 8];
            float4 b1 = *(const float4*)&Bs[k][tx * 8 + 4];
            float a[8]  = {a0.x, a0.y, a0.z, a0.w, a1.x, a1.y, a1.z, a1.w};
            float bb[8] = {b0.x, b0.y, b0.z, b0.w, b1.x, b1.y, b1.z, b1.w};
            #pragma unroll
            for (int i = 0; i < 8; i++)
                #pragma unroll
                for (int j = 0; j < 8; j++)
                    acc[i][j] = fmaf(a[i], bb[j], acc[i][j]);
        }
        __syncthreads();
    }

    #pragma unroll
    for (int i = 0; i < 8; i++) {
        int row = row0 + ty * 8 + i;
        #pragma unroll
        for (int jj = 0; jj < 2; jj++) {
            int col = col0 + tx * 8 + jj * 4;
            float4 bi = *(const float4*)(bias + col);
            float4 v;
            v.x = acc[i][jj * 4 + 0] + bi.x;
            v.y = acc[i][jj * 4 + 1] + bi.y;
            v.z = acc[i][jj * 4 + 2] + bi.z;
            v.w = acc[i][jj * 4 + 3] + bi.w;
            if (EPI == 1) {
                v.x = v.x / (1.0f + __expf(-1.702f * v.x));
                v.y = v.y / (1.0f + __expf(-1.702f * v.y));
                v.z = v.z / (1.0f + __expf(-1.702f * v.z));
                v.w = v.w / (1.0f + __expf(-1.702f * v.w));
            }
            if (EPI == 2) {
                float4 r = *(const float4*)(res + (size_t)row * N + col);
                v.x += r.x; v.y += r.y; v.z += r.z; v.w += r.w;
            }
            *(float4*)(C + (size_t)row * N + col) = v;
        }
    }
}

// ---------------- Flash attention (fp32, 64x64 tiles, DH=64) ----------------
// qkv layout per token: [q(1024) | k(1024) | v(1024)], head h at offset h*64.
__global__ __launch_bounds__(256) void attn_kernel(
    const float* __restrict__ qkv, float* __restrict__ o, int tok0, int N)
{
    __shared__ float Qt[64 * 64];   // [d][row], pre-scaled
    __shared__ float KP[64 * 64];   // Kt [d][row], then P [row][col]
    __shared__ float Vs[64 * 64];   // [k][d]

    int tid = threadIdx.x, tx = tid & 15, ty = tid >> 4;
    int h    = blockIdx.y;
    int base = tok0 + blockIdx.z * N;
    int q0   = blockIdx.x * 64;
    int lr = tid >> 2, lp = (tid & 3) * 16;

    // load Q tile transposed, scaled by 1/sqrt(64)
    {
        const float* src = qkv + (size_t)(base + q0 + lr) * 3072 + h * 64 + lp;
        #pragma unroll
        for (int i = 0; i < 4; i++) {
            float4 v = *(const float4*)(src + i * 4);
            int d = lp + i * 4;
            Qt[(d + 0) * 64 + lr] = v.x * 0.125f;
            Qt[(d + 1) * 64 + lr] = v.y * 0.125f;
            Qt[(d + 2) * 64 + lr] = v.z * 0.125f;
            Qt[(d + 3) * 64 + lr] = v.w * 0.125f;
        }
    }

    float m[4], l[4], oa[4][4];
    #pragma unroll
    for (int i = 0; i < 4; i++) {
        m[i] = -1e30f; l[i] = 0.f;
        #pragma unroll
        for (int j = 0; j < 4; j++) oa[i][j] = 0.f;
    }

    for (int kt = 0; kt < N; kt += 64) {
        __syncthreads();   // prev-iter PV reads of KP/Vs done; Q stores done (iter 0)
        {
            const float* ks = qkv + (size_t)(base + kt + lr) * 3072 + 1024 + h * 64 + lp;
            #pragma unroll
            for (int i = 0; i < 4; i++) {
                float4 kv = *(const float4*)(ks + i * 4);
                int d = lp + i * 4;
                KP[(d + 0) * 64 + lr] = kv.x;
                KP[(d + 1) * 64 + lr] = kv.y;
                KP[(d + 2) * 64 + lr] = kv.z;
                KP[(d + 3) * 64 + lr] = kv.w;
            }
            const float* vsp = ks + 1024;
            #pragma unroll
            for (int i = 0; i < 4; i++)
                *(float4*)&Vs[lr * 64 + lp + i * 4] = *(const float4*)(vsp + i * 4);
        }
        __syncthreads();

        // S = Q K^T  (4x4 per thread)
        float s[4][4];
        #pragma unroll
        for (int i = 0; i < 4; i++)
            #pragma unroll
            for (int j = 0; j < 4; j++) s[i][j] = 0.f;
        #pragma unroll 8
        for (int d = 0; d < 64; d++) {
            float4 a = *(const float4*)&Qt[d * 64 + ty * 4];
            float4 b = *(const float4*)&KP[d * 64 + tx * 4];
            s[0][0] = fmaf(a.x, b.x, s[0][0]); s[0][1] = fmaf(a.x, b.y, s[0][1]);
            s[0][2] = fmaf(a.x, b.z, s[0][2]); s[0][3] = fmaf(a.x, b.w, s[0][3]);
            s[1][0] = fmaf(a.y, b.x, s[1][0]); s[1][1] = fmaf(a.y, b.y, s[1][1]);
            s[1][2] = fmaf(a.y, b.z, s[1][2]); s[1][3] = fmaf(a.y, b.w, s[1][3]);
            s[2][0] = fmaf(a.z, b.x, s[2][0]); s[2][1] = fmaf(a.z, b.y, s[2][1]);
            s[2][2] = fmaf(a.z, b.z, s[2][2]); s[2][3] = fmaf(a.z, b.w, s[2][3]);
            s[3][0] = fmaf(a.w, b.x, s[3][0]); s[3][1] = fmaf(a.w, b.y, s[3][1]);
            s[3][2] = fmaf(a.w, b.z, s[3][2]); s[3][3] = fmaf(a.w, b.w, s[3][3]);
        }

        // online softmax: row stats via 16-lane shuffles (rows owned by same-ty lanes)
        #pragma unroll
        for (int i = 0; i < 4; i++) {
            float tmax = fmaxf(fmaxf(s[i][0], s[i][1]), fmaxf(s[i][2], s[i][3]));
            #pragma unroll
            for (int off = 8; off > 0; off >>= 1)
                tmax = fmaxf(tmax, __shfl_xor_sync(0xffffffffu, tmax, off));
            float mn = fmaxf(m[i], tmax);
            float al = __expf(m[i] - mn);
            m[i] = mn;
            float rs = 0.f;
            #pragma unroll
            for (int j = 0; j < 4; j++) { s[i][j] = __expf(s[i][j] - mn); rs += s[i][j]; }
            #pragma unroll
            for (int off = 8; off > 0; off >>= 1)
                rs += __shfl_xor_sync(0xffffffffu, rs, off);
            l[i] = l[i] * al + rs;
            #pragma unroll
            for (int j = 0; j < 4; j++) oa[i][j] *= al;
        }

        __syncthreads();   // all Kt reads done; safe to overwrite KP with P
        #pragma unroll
        for (int i = 0; i < 4; i++)
            *(float4*)&KP[(ty * 4 + i) * 64 + tx * 4] =
                make_float4(s[i][0], s[i][1], s[i][2], s[i][3]);
        __syncthreads();

        // O += P @ V
        #pragma unroll 4
        for (int k = 0; k < 64; k++) {
            float4 v = *(const float4*)&Vs[k * 64 + tx * 4];
            #pragma unroll
            for (int i = 0; i < 4; i++) {
                float p = KP[(ty * 4 + i) * 64 + k];
                oa[i][0] = fmaf(p, v.x, oa[i][0]);
                oa[i][1] = fmaf(p, v.y, oa[i][1]);
                oa[i][2] = fmaf(p, v.z, oa[i][2]);
                oa[i][3] = fmaf(p, v.w, oa[i][3]);
            }
        }
    }

    #pragma unroll
    for (int i = 0; i < 4; i++) {
        float inv = 1.0f / l[i];
        int row = base + q0 + ty * 4 + i;
        float4 v = make_float4(oa[i][0] * inv, oa[i][1] * inv,
                               oa[i][2] * inv, oa[i][3] * inv);
        *(float4*)(o + (size_t)row * 1024 + h * 64 + tx * 4) = v;
    }
}

// ---------------- launch ----------------
extern "C" void kernel_launch(void* const* d_in, const int* in_sizes, int n_in,
                              void* d_out, int out_size)
{
    const float* x1    = (const float*)d_in[0];
    const float* x2    = (const float*)d_in[1];
    const float* w_qkv = (const float*)d_in[2];
    const float* b_qkv = (const float*)d_in[3];
    const float* w_o   = (const float*)d_in[4];
    const float* b_o   = (const float*)d_in[5];
    const float* g1    = (const float*)d_in[6];
    const float* be1   = (const float*)d_in[7];
    const float* w_fc  = (const float*)d_in[8];
    const float* b_fc  = (const float*)d_in[9];
    const float* w_pr  = (const float*)d_in[10];
    const float* b_pr  = (const float*)d_in[11];
    const float* g2    = (const float*)d_in[12];
    const float* be2   = (const float*)d_in[13];
    float* out = (float*)d_out;

    float *xcat, *h, *qkvb, *ob, *xa, *ub;
    cudaGetSymbolAddress((void**)&xcat, g_xcat);
    cudaGetSymbolAddress((void**)&h,    g_h);
    cudaGetSymbolAddress((void**)&qkvb, g_qkv);
    cudaGetSymbolAddress((void**)&ob,   g_o);
    cudaGetSymbolAddress((void**)&xa,   g_xa);
    cudaGetSymbolAddress((void**)&ub,   g_u);

    // concat tokens: x1 (8192) then x2 (4096)
    cudaMemcpyAsync(xcat, x1, (size_t)T1 * D * sizeof(float),
                    cudaMemcpyDeviceToDevice, 0);
    cudaMemcpyAsync(xcat + (size_t)T1 * D, x2, (size_t)T2 * D * sizeof(float),
                    cudaMemcpyDeviceToDevice, 0);

    // LN1
    ln_kernel<<<TT, 256>>>(xcat, g1, be1, h);
    // QKV projection
    sgemm_kernel<0><<<dim3(3072 / 128, TT / 128), 256>>>(
        h, w_qkv, b_qkv, nullptr, qkvb, TT, 3072, 1024);
    // attention: x1 part (8 seqs of 1024) and x2 part (16 seqs of 256)
    attn_kernel<<<dim3(16, 16, 8),  256>>>(qkvb, ob, 0,  1024);
    attn_kernel<<<dim3(4,  16, 16), 256>>>(qkvb, ob, T1, 256);
    // out projection + residual
    sgemm_kernel<2><<<dim3(1024 / 128, TT / 128), 256>>>(
        ob, w_o, b_o, xcat, xa, TT, 1024, 1024);
    // LN2
    ln_kernel<<<TT, 256>>>(xa, g2, be2, h);
    // FC + QuickGELU
    sgemm_kernel<1><<<dim3(4096 / 128, TT / 128), 256>>>(
        h, w_fc, b_fc, nullptr, ub, TT, 4096, 1024);
    // projection + residual -> output
    sgemm_kernel<2><<<dim3(1024 / 128, TT / 128), 256>>>(
        ub, w_pr, b_pr, xa, out, TT, 1024, 4096);
}

// round 3
// speedup vs baseline: 2.5357x; 2.5357x over previous
#include <cuda_runtime.h>
#include <math.h>
#include <stdint.h>

#define D   1024
#define T1  8192
#define T2  4096
#define TT  12288

// GEMM tiling (mma.sync tf32 path; tcgen05 PTX unavailable on plain sm_103 target)
#define BM 128
#define BN 128
#define BK 32
#define PAD 4
#define ROWF (BK + PAD)                       // 36 floats per SMEM row
#define STAGE_FLOATS (2 * BM * ROWF)          // A tile + B tile
#define STAGE_BYTES  (STAGE_FLOATS * 4)       // 36864
#define GEMM_SMEM    (2 * STAGE_BYTES)        // 73728 (double buffer)

// -------- scratch (device globals; no allocation anywhere) --------
__device__ float g_xcat[TT * D];
__device__ float g_h[TT * D];
__device__ float g_qkv[TT * 3 * D];
__device__ float g_o[TT * D];
__device__ float g_xa[TT * D];
__device__ float g_u[TT * 4 * D];
// transposed weights [N][K]
__device__ float g_wqkv_t[3 * D * D];
__device__ float g_wo_t[D * D];
__device__ float g_wfc_t[4 * D * D];
__device__ float g_wpr_t[D * 4 * D];

// ---------------- small helpers ----------------
__device__ __forceinline__ uint32_t smem_u32(const void* p) {
    uint32_t a;
    asm("{ .reg .u64 t; cvta.to.shared.u64 t, %1; cvt.u32.u64 %0, t; }"
        : "=r"(a) : "l"(p));
    return a;
}
__device__ __forceinline__ float to_tf32(float x) {
    uint32_t u;
    asm("cvt.rna.tf32.f32 %0, %1;" : "=r"(u) : "f"(x));
    return __uint_as_float(u);
}
__device__ __forceinline__ void cp16(uint32_t s, const void* g) {
    asm volatile("cp.async.cg.shared.global [%0], [%1], 16;" :: "r"(s), "l"(g));
}
__device__ __forceinline__ void cp_commit() {
    asm volatile("cp.async.commit_group;");
}

// ---------------- transpose (W[K][N] -> WT[N][K], tf32-rounded) ----------------
__global__ __launch_bounds__(256) void transpose_kernel(
    const float* __restrict__ in, float* __restrict__ out, int K, int N)
{
    __shared__ float t[32][33];
    int n0 = blockIdx.x * 32, k0 = blockIdx.y * 32;
    int x = threadIdx.x, y = threadIdx.y;   // 32 x 8
    #pragma unroll
    for (int i = 0; i < 32; i += 8)
        t[y + i][x] = in[(size_t)(k0 + y + i) * N + n0 + x];
    __syncthreads();
    #pragma unroll
    for (int i = 0; i < 32; i += 8)
        out[(size_t)(n0 + y + i) * K + k0 + x] = to_tf32(t[x][y + i]);
}

// ---------------- HMMA tf32 GEMM: C = A[MxK] @ BT[NxK]^T (+epilogue) ----------
// EPI: 0 = bias, 1 = bias + QuickGELU (+tf32 round), 2 = bias + residual
template<int EPI>
__global__ __launch_bounds__(256, 2) void mma_gemm(
    const float* __restrict__ A, const float* __restrict__ Bt,
    const float* __restrict__ bias, const float* __restrict__ res,
    float* __restrict__ C, int N, int K)
{
    extern __shared__ float sm[];
    const int tid = threadIdx.x, wid = tid >> 5, lane = tid & 31;
    const int m0 = blockIdx.y * BM, n0 = blockIdx.x * BN;
    const int wr = wid & 3, wc = wid >> 2;          // warp grid 4 (M) x 2 (N)
    const int g = lane >> 2, tq = lane & 3;         // group row, quad lane

    float c[2][8][4];
    #pragma unroll
    for (int mt = 0; mt < 2; mt++)
        #pragma unroll
        for (int nt = 0; nt < 8; nt++)
            #pragma unroll
            for (int j = 0; j < 4; j++) c[mt][nt][j] = 0.f;

    auto load_stage = [&](int s, int kb) {
        float* sA = sm + s * STAGE_FLOATS;
        float* sB = sA + BM * ROWF;
        const float* gA = A  + (size_t)m0 * K + kb * BK;
        const float* gB = Bt + (size_t)n0 * K + kb * BK;
        #pragma unroll
        for (int t = 0; t < 4; t++) {
            int ch = tid + t * 256;
            int r = ch >> 3, kc = ch & 7;
            cp16(smem_u32(sA + r * ROWF + kc * 4), gA + (size_t)r * K + kc * 4);
        }
        #pragma unroll
        for (int t = 0; t < 4; t++) {
            int ch = tid + t * 256;
            int r = ch >> 3, kc = ch & 7;
            cp16(smem_u32(sB + r * ROWF + kc * 4), gB + (size_t)r * K + kc * 4);
        }
    };

    const int iters = K / BK;
    load_stage(0, 0);
    cp_commit();

    for (int i = 0; i < iters; i++) {
        if (i + 1 < iters) {
            load_stage((i + 1) & 1, i + 1);
            cp_commit();
            asm volatile("cp.async.wait_group 1;");
        } else {
            asm volatile("cp.async.wait_group 0;");
        }
        __syncthreads();

        const float* sA = sm + (i & 1) * STAGE_FLOATS;
        const float* sB = sA + BM * ROWF;

        #pragma unroll
        for (int k0 = 0; k0 < BK; k0 += 8) {
            uint32_t a[2][4];
            #pragma unroll
            for (int mt = 0; mt < 2; mt++) {
                const float* p = sA + (wr * 32 + mt * 16 + g) * ROWF + k0 + tq;
                a[mt][0] = __float_as_uint(p[0]);
                a[mt][1] = __float_as_uint(p[8 * ROWF]);
                a[mt][2] = __float_as_uint(p[4]);
                a[mt][3] = __float_as_uint(p[8 * ROWF + 4]);
            }
            uint32_t b[8][2];
            #pragma unroll
            for (int nt = 0; nt < 8; nt++) {
                const float* p = sB + (wc * 64 + nt * 8 + g) * ROWF + k0 + tq;
                b[nt][0] = __float_as_uint(p[0]);
                b[nt][1] = __float_as_uint(p[4]);
            }
            #pragma unroll
            for (int mt = 0; mt < 2; mt++)
                #pragma unroll
                for (int nt = 0; nt < 8; nt++)
                    asm volatile(
                        "mma.sync.aligned.m16n8k8.row.col.f32.tf32.tf32.f32 "
                        "{%0,%1,%2,%3}, {%4,%5,%6,%7}, {%8,%9}, {%0,%1,%2,%3};"
                        : "+f"(c[mt][nt][0]), "+f"(c[mt][nt][1]),
                          "+f"(c[mt][nt][2]), "+f"(c[mt][nt][3])
                        : "r"(a[mt][0]), "r"(a[mt][1]), "r"(a[mt][2]), "r"(a[mt][3]),
                          "r"(b[nt][0]), "r"(b[nt][1]));
        }
        __syncthreads();
    }

    // epilogue: c0,c1 -> row rb, cols 2tq..2tq+1 ; c2,c3 -> row rb+8
    #pragma unroll
    for (int mt = 0; mt < 2; mt++) {
        size_t rb = (size_t)(m0 + wr * 32 + mt * 16 + g);
        #pragma unroll
        for (int nt = 0; nt < 8; nt++) {
            int col = n0 + wc * 64 + nt * 8 + tq * 2;
            float2 bi = *(const float2*)(bias + col);
            float v0 = c[mt][nt][0] + bi.x;
            float v1 = c[mt][nt][1] + bi.y;
            float v2 = c[mt][nt][2] + bi.x;
            float v3 = c[mt][nt][3] + bi.y;
            if (EPI == 1) {
                v0 = to_tf32(v0 / (1.0f + __expf(-1.702f * v0)));
                v1 = to_tf32(v1 / (1.0f + __expf(-1.702f * v1)));
                v2 = to_tf32(v2 / (1.0f + __expf(-1.702f * v2)));
                v3 = to_tf32(v3 / (1.0f + __expf(-1.702f * v3)));
            }
            if (EPI == 2) {
                float2 r0 = *(const float2*)(res + rb * N + col);
                float2 r1 = *(const float2*)(res + (rb + 8) * N + col);
                v0 += r0.x; v1 += r0.y; v2 += r1.x; v3 += r1.y;
            }
            *(float2*)(C + rb * N + col)       = make_float2(v0, v1);
            *(float2*)(C + (rb + 8) * N + col) = make_float2(v2, v3);
        }
    }
}

// ---------------- LayerNorm (tf32-rounded output) ----------------
__global__ __launch_bounds__(256) void ln_kernel(
    const float* __restrict__ x, const float* __restrict__ g,
    const float* __restrict__ b, float* __restrict__ out)
{
    int t = blockIdx.x;
    const float4* xr = (const float4*)(x + (size_t)t * D);
    float4 v = xr[threadIdx.x];
    float s  = v.x + v.y + v.z + v.w;
    float s2 = v.x*v.x + v.y*v.y + v.z*v.z + v.w*v.w;
    #pragma unroll
    for (int o = 16; o > 0; o >>= 1) {
        s  += __shfl_xor_sync(0xffffffffu, s,  o);
        s2 += __shfl_xor_sync(0xffffffffu, s2, o);
    }
    __shared__ float2 wr[8];
    __shared__ float2 stat;
    int warp = threadIdx.x >> 5, lane = threadIdx.x & 31;
    if (lane == 0) wr[warp] = make_float2(s, s2);
    __syncthreads();
    if (threadIdx.x == 0) {
        float ts = 0.f, ts2 = 0.f;
        #pragma unroll
        for (int i = 0; i < 8; i++) { ts += wr[i].x; ts2 += wr[i].y; }
        float mu  = ts * (1.0f / D);
        float var = ts2 * (1.0f / D) - mu * mu;
        stat = make_float2(mu, rsqrtf(var + 1e-5f));
    }
    __syncthreads();
    float mu = stat.x, rstd = stat.y;
    float4 gv = ((const float4*)g)[threadIdx.x];
    float4 bv = ((const float4*)b)[threadIdx.x];
    float4 o4;
    o4.x = to_tf32((v.x - mu) * rstd * gv.x + bv.x);
    o4.y = to_tf32((v.y - mu) * rstd * gv.y + bv.y);
    o4.z = to_tf32((v.z - mu) * rstd * gv.z + bv.z);
    o4.w = to_tf32((v.w - mu) * rstd * gv.w + bv.w);
    ((float4*)(out + (size_t)t * D))[threadIdx.x] = o4;
}

// ---------------- Flash attention (fp32, 64x64 tiles, DH=64) ----------------
__global__ __launch_bounds__(256) void attn_kernel(
    const float* __restrict__ qkv, float* __restrict__ o, int tok0, int N)
{
    __shared__ float Qt[64 * 64];
    __shared__ float KP[64 * 64];
    __shared__ float Vs[64 * 64];

    int tid = threadIdx.x, tx = tid & 15, ty = tid >> 4;
    int h    = blockIdx.y;
    int base = tok0 + blockIdx.z * N;
    int q0   = blockIdx.x * 64;
    int lr = tid >> 2, lp = (tid & 3) * 16;

    {
        const float* src = qkv + (size_t)(base + q0 + lr) * 3072 + h * 64 + lp;
        #pragma unroll
        for (int i = 0; i < 4; i++) {
            float4 v = *(const float4*)(src + i * 4);
            int d = lp + i * 4;
            Qt[(d + 0) * 64 + lr] = v.x * 0.125f;
            Qt[(d + 1) * 64 + lr] = v.y * 0.125f;
            Qt[(d + 2) * 64 + lr] = v.z * 0.125f;
            Qt[(d + 3) * 64 + lr] = v.w * 0.125f;
        }
    }

    float m[4], l[4], oa[4][4];
    #pragma unroll
    for (int i = 0; i < 4; i++) {
        m[i] = -1e30f; l[i] = 0.f;
        #pragma unroll
        for (int j = 0; j < 4; j++) oa[i][j] = 0.f;
    }

    for (int kt = 0; kt < N; kt += 64) {
        __syncthreads();
        {
            const float* ks = qkv + (size_t)(base + kt + lr) * 3072 + 1024 + h * 64 + lp;
            #pragma unroll
            for (int i = 0; i < 4; i++) {
                float4 kv = *(const float4*)(ks + i * 4);
                int d = lp + i * 4;
                KP[(d + 0) * 64 + lr] = kv.x;
                KP[(d + 1) * 64 + lr] = kv.y;
                KP[(d + 2) * 64 + lr] = kv.z;
                KP[(d + 3) * 64 + lr] = kv.w;
            }
            const float* vsp = ks + 1024;
            #pragma unroll
            for (int i = 0; i < 4; i++)
                *(float4*)&Vs[lr * 64 + lp + i * 4] = *(const float4*)(vsp + i * 4);
        }
        __syncthreads();

        float s[4][4];
        #pragma unroll
        for (int i = 0; i < 4; i++)
            #pragma unroll
            for (int j = 0; j < 4; j++) s[i][j] = 0.f;
        #pragma unroll 8
        for (int d = 0; d < 64; d++) {
            float4 a = *(const float4*)&Qt[d * 64 + ty * 4];
            float4 b = *(const float4*)&KP[d * 64 + tx * 4];
            s[0][0] = fmaf(a.x, b.x, s[0][0]); s[0][1] = fmaf(a.x, b.y, s[0][1]);
            s[0][2] = fmaf(a.x, b.z, s[0][2]); s[0][3] = fmaf(a.x, b.w, s[0][3]);
            s[1][0] = fmaf(a.y, b.x, s[1][0]); s[1][1] = fmaf(a.y, b.y, s[1][1]);
            s[1][2] = fmaf(a.y, b.z, s[1][2]); s[1][3] = fmaf(a.y, b.w, s[1][3]);
            s[2][0] = fmaf(a.z, b.x, s[2][0]); s[2][1] = fmaf(a.z, b.y, s[2][1]);
            s[2][2] = fmaf(a.z, b.z, s[2][2]); s[2][3] = fmaf(a.z, b.w, s[2][3]);
            s[3][0] = fmaf(a.w, b.x, s[3][0]); s[3][1] = fmaf(a.w, b.y, s[3][1]);
            s[3][2] = fmaf(a.w, b.z, s[3][2]); s[3][3] = fmaf(a.w, b.w, s[3][3]);
        }

        #pragma unroll
        for (int i = 0; i < 4; i++) {
            float tmax = fmaxf(fmaxf(s[i][0], s[i][1]), fmaxf(s[i][2], s[i][3]));
            #pragma unroll
            for (int off = 8; off > 0; off >>= 1)
                tmax = fmaxf(tmax, __shfl_xor_sync(0xffffffffu, tmax, off));
            float mn = fmaxf(m[i], tmax);
            float al = __expf(m[i] - mn);
            m[i] = mn;
            float rs = 0.f;
            #pragma unroll
            for (int j = 0; j < 4; j++) { s[i][j] = __expf(s[i][j] - mn); rs += s[i][j]; }
            #pragma unroll
            for (int off = 8; off > 0; off >>= 1)
                rs += __shfl_xor_sync(0xffffffffu, rs, off);
            l[i] = l[i] * al + rs;
            #pragma unroll
            for (int j = 0; j < 4; j++) oa[i][j] *= al;
        }

        __syncthreads();
        #pragma unroll
        for (int i = 0; i < 4; i++)
            *(float4*)&KP[(ty * 4 + i) * 64 + tx * 4] =
                make_float4(s[i][0], s[i][1], s[i][2], s[i][3]);
        __syncthreads();

        #pragma unroll 4
        for (int k = 0; k < 64; k++) {
            float4 v = *(const float4*)&Vs[k * 64 + tx * 4];
            #pragma unroll
            for (int i = 0; i < 4; i++) {
                float p = KP[(ty * 4 + i) * 64 + k];
                oa[i][0] = fmaf(p, v.x, oa[i][0]);
                oa[i][1] = fmaf(p, v.y, oa[i][1]);
                oa[i][2] = fmaf(p, v.z, oa[i][2]);
                oa[i][3] = fmaf(p, v.w, oa[i][3]);
            }
        }
    }

    #pragma unroll
    for (int i = 0; i < 4; i++) {
        float inv = 1.0f / l[i];
        int row = base + q0 + ty * 4 + i;
        float4 v = make_float4(to_tf32(oa[i][0] * inv), to_tf32(oa[i][1] * inv),
                               to_tf32(oa[i][2] * inv), to_tf32(oa[i][3] * inv));
        *(float4*)(o + (size_t)row * 1024 + h * 64 + tx * 4) = v;
    }
}

// ---------------- launch ----------------
extern "C" void kernel_launch(void* const* d_in, const int* in_sizes, int n_in,
                              void* d_out, int out_size)
{
    const float* x1    = (const float*)d_in[0];
    const float* x2    = (const float*)d_in[1];
    const float* w_qkv = (const float*)d_in[2];
    const float* b_qkv = (const float*)d_in[3];
    const float* w_o   = (const float*)d_in[4];
    const float* b_o   = (const float*)d_in[5];
    const float* g1    = (const float*)d_in[6];
    const float* be1   = (const float*)d_in[7];
    const float* w_fc  = (const float*)d_in[8];
    const float* b_fc  = (const float*)d_in[9];
    const float* w_pr  = (const float*)d_in[10];
    const float* b_pr  = (const float*)d_in[11];
    const float* g2    = (const float*)d_in[12];
    const float* be2   = (const float*)d_in[13];
    float* out = (float*)d_out;

    float *xcat, *h, *qkvb, *ob, *xa, *ub;
    float *wqkv_t, *wo_t, *wfc_t, *wpr_t;
    cudaGetSymbolAddress((void**)&xcat,   g_xcat);
    cudaGetSymbolAddress((void**)&h,      g_h);
    cudaGetSymbolAddress((void**)&qkvb,   g_qkv);
    cudaGetSymbolAddress((void**)&ob,     g_o);
    cudaGetSymbolAddress((void**)&xa,     g_xa);
    cudaGetSymbolAddress((void**)&ub,     g_u);
    cudaGetSymbolAddress((void**)&wqkv_t, g_wqkv_t);
    cudaGetSymbolAddress((void**)&wo_t,   g_wo_t);
    cudaGetSymbolAddress((void**)&wfc_t,  g_wfc_t);
    cudaGetSymbolAddress((void**)&wpr_t,  g_wpr_t);

    cudaFuncSetAttribute(mma_gemm<0>, cudaFuncAttributeMaxDynamicSharedMemorySize, GEMM_SMEM);
    cudaFuncSetAttribute(mma_gemm<1>, cudaFuncAttributeMaxDynamicSharedMemorySize, GEMM_SMEM);
    cudaFuncSetAttribute(mma_gemm<2>, cudaFuncAttributeMaxDynamicSharedMemorySize, GEMM_SMEM);

    // concat tokens
    cudaMemcpyAsync(xcat, x1, (size_t)T1 * D * sizeof(float),
                    cudaMemcpyDeviceToDevice, 0);
    cudaMemcpyAsync(xcat + (size_t)T1 * D, x2, (size_t)T2 * D * sizeof(float),
                    cudaMemcpyDeviceToDevice, 0);

    // weight transposes (tf32-rounded)
    transpose_kernel<<<dim3(3072 / 32, 1024 / 32), dim3(32, 8)>>>(w_qkv, wqkv_t, 1024, 3072);
    transpose_kernel<<<dim3(1024 / 32, 1024 / 32), dim3(32, 8)>>>(w_o,   wo_t,   1024, 1024);
    transpose_kernel<<<dim3(4096 / 32, 1024 / 32), dim3(32, 8)>>>(w_fc,  wfc_t,  1024, 4096);
    transpose_kernel<<<dim3(1024 / 32, 4096 / 32), dim3(32, 8)>>>(w_pr,  wpr_t,  4096, 1024);

    // LN1
    ln_kernel<<<TT, 256>>>(xcat, g1, be1, h);
    // QKV projection
    mma_gemm<0><<<dim3(3072 / BN, TT / BM), 256, GEMM_SMEM>>>(
        h, wqkv_t, b_qkv, nullptr, qkvb, 3072, 1024);
    // attention
    attn_kernel<<<dim3(16, 16, 8),  256>>>(qkvb, ob, 0,  1024);
    attn_kernel<<<dim3(4,  16, 16), 256>>>(qkvb, ob, T1, 256);
    // out projection + residual
    mma_gemm<2><<<dim3(1024 / BN, TT / BM), 256, GEMM_SMEM>>>(
        ob, wo_t, b_o, xcat, xa, 1024, 1024);
    // LN2
    ln_kernel<<<TT, 256>>>(xa, g2, be2, h);
    // FC + QuickGELU
    mma_gemm<1><<<dim3(4096 / BN, TT / BM), 256, GEMM_SMEM>>>(
        h, wfc_t, b_fc, nullptr, ub, 4096, 1024);
    // projection + residual -> output
    mma_gemm<2><<<dim3(1024 / BN, TT / BM), 256, GEMM_SMEM>>>(
        ub, wpr_t, b_pr, xa, out, 1024, 4096);
}